// round 3
// baseline (speedup 1.0000x reference)
#include <cuda_runtime.h>
#include <math.h>
#include <float.h>

#define N_NODES 100000
#define N_EDGES 1600000
#define FDIM 64
#define N_GRAPHS 64
#define EPSV 1e-5f

// ---------------- scratch (device globals; no allocation allowed) ----------
__device__ float g_deg[N_NODES];                 // deg, then deg^{-1/2} in place
__device__ float g_norm[N_EDGES];                // per-edge normalization
__device__ float g_h[3][N_NODES * FDIM];         // h1, h2, h3 (hop results)
__device__ float g_out[N_NODES * FDIM];          // TAGConv output accumulator

// ---------------- zero scratch (deg + all hop buffers) ---------------------
__global__ void zero_kernel(float* __restrict__ p, long n4 /* float4 count */) {
    long i = threadIdx.x + (long)blockIdx.x * blockDim.x;
    long stride = (long)gridDim.x * blockDim.x;
    float4* p4 = (float4*)p;
    for (long j = i; j < n4; j += stride) p4[j] = make_float4(0.f, 0.f, 0.f, 0.f);
}

// ---------------- degree: deg[dst] += w ------------------------------------
__global__ void deg_kernel(const int* __restrict__ dst, const float* __restrict__ ew,
                           float* __restrict__ deg) {
    int e = blockIdx.x * blockDim.x + threadIdx.x;
    if (e < N_EDGES) atomicAdd(&deg[dst[e]], ew[e]);
}

// ---------------- deg -> deg^{-1/2} (0 where deg==0) -----------------------
__global__ void dis_kernel(float* __restrict__ deg) {
    int i = blockIdx.x * blockDim.x + threadIdx.x;
    if (i < N_NODES) {
        float d = deg[i];
        deg[i] = (d > 0.f) ? rsqrtf(d) : 0.f;
    }
}

// ---------------- norm[e] = dis[src]*w*dis[dst] ----------------------------
__global__ void norm_kernel(const int* __restrict__ src, const int* __restrict__ dst,
                            const float* __restrict__ ew,
                            const float* __restrict__ dis, float* __restrict__ nrm) {
    int e = blockIdx.x * blockDim.x + threadIdx.x;
    if (e < N_EDGES) nrm[e] = dis[src[e]] * ew[e] * dis[dst[e]];
}

// ---------------- SpMM hop: hout[dst] += norm * hin[src] -------------------
// 16 threads per edge, each handles a float4 feature chunk; scatter via
// red.global.add.v4.f32 (sm_90+) -> 4x fewer red lane-ops than scalar atomics.
__global__ __launch_bounds__(256) void spmm_kernel(
        const float* __restrict__ hin, float* __restrict__ hout,
        const int* __restrict__ src, const int* __restrict__ dst,
        const float* __restrict__ nrm) {
    int t = blockIdx.x * blockDim.x + threadIdx.x;
    int e = t >> 4;
    int c = t & 15;
    if (e >= N_EDGES) return;
    int s = src[e];
    int d = dst[e];
    float nm = nrm[e];
    float4 v = *(const float4*)(hin + (long)s * FDIM + c * 4);
    v.x *= nm; v.y *= nm; v.z *= nm; v.w *= nm;
    float* addr = hout + (long)d * FDIM + c * 4;
    asm volatile("red.global.add.v4.f32 [%0], {%1, %2, %3, %4};"
                 :: "l"(addr), "f"(v.x), "f"(v.y), "f"(v.z), "f"(v.w)
                 : "memory");
}

// ---------------- dense pass: out (+)= H @ Wk (+ b on last pass) -----------
// Warp handles 2 nodes. Each lane owns output features (2*lane, 2*lane+1).
// Row elements broadcast via shfl; Wk (16KB) staged in smem.
__global__ __launch_bounds__(256) void gemm_kernel(
        const float* __restrict__ H, const float* __restrict__ Wk,
        const float* __restrict__ b, float* __restrict__ out,
        int accumulate, int addbias) {
    __shared__ float Ws[FDIM * FDIM];
    __shared__ float bs[FDIM];
    for (int i = threadIdx.x; i < FDIM * FDIM; i += blockDim.x) Ws[i] = Wk[i];
    if (addbias && threadIdx.x < FDIM) bs[threadIdx.x] = b[threadIdx.x];
    __syncthreads();

    int warp = threadIdx.x >> 5;
    int lane = threadIdx.x & 31;
    int wpb = blockDim.x >> 5;
    long stride = (long)gridDim.x * wpb * 2;

    for (long n0 = ((long)blockIdx.x * wpb + warp) * 2; n0 < N_NODES; n0 += stride) {
        // N_NODES is even -> always a full pair
        float rlo0 = H[n0 * FDIM + lane];
        float rhi0 = H[n0 * FDIM + lane + 32];
        float rlo1 = H[(n0 + 1) * FDIM + lane];
        float rhi1 = H[(n0 + 1) * FDIM + lane + 32];
        float2 acc0 = make_float2(0.f, 0.f);
        float2 acc1 = make_float2(0.f, 0.f);

#pragma unroll
        for (int j = 0; j < 32; j++) {
            float2 w = *(const float2*)&Ws[j * FDIM + lane * 2];
            float a0 = __shfl_sync(0xffffffffu, rlo0, j);
            float a1 = __shfl_sync(0xffffffffu, rlo1, j);
            acc0.x = fmaf(a0, w.x, acc0.x); acc0.y = fmaf(a0, w.y, acc0.y);
            acc1.x = fmaf(a1, w.x, acc1.x); acc1.y = fmaf(a1, w.y, acc1.y);
        }
#pragma unroll
        for (int j = 0; j < 32; j++) {
            float2 w = *(const float2*)&Ws[(j + 32) * FDIM + lane * 2];
            float a0 = __shfl_sync(0xffffffffu, rhi0, j);
            float a1 = __shfl_sync(0xffffffffu, rhi1, j);
            acc0.x = fmaf(a0, w.x, acc0.x); acc0.y = fmaf(a0, w.y, acc0.y);
            acc1.x = fmaf(a1, w.x, acc1.x); acc1.y = fmaf(a1, w.y, acc1.y);
        }

        float bx = 0.f, by = 0.f;
        if (addbias) { bx = bs[2 * lane]; by = bs[2 * lane + 1]; }

        float2* o0 = (float2*)(out + n0 * FDIM) + lane;
        float2* o1 = (float2*)(out + (n0 + 1) * FDIM) + lane;
        float2 p0 = accumulate ? *o0 : make_float2(0.f, 0.f);
        float2 p1 = accumulate ? *o1 : make_float2(0.f, 0.f);
        *o0 = make_float2(p0.x + acc0.x + bx, p0.y + acc0.y + by);
        *o1 = make_float2(p1.x + acc1.x + bx, p1.y + acc1.y + by);
    }
}

// ---------------- GraphNorm + residual ReLU + mean/max pool ----------------
// One block per graph (batch is sorted -> contiguous node range via bsearch).
// 1024 threads: f = tid&63, 16 node-lanes.
__global__ __launch_bounds__(1024) void norm_pool_kernel(
        const float* __restrict__ outv, const float* __restrict__ x,
        const int* __restrict__ batch,
        const float* __restrict__ gw, const float* __restrict__ gb,
        const float* __restrict__ gms,
        float* __restrict__ hemb, float* __restrict__ flat) {
    int g = blockIdx.x;

    // lower_bound(batch, g) and lower_bound(batch, g+1)
    int lo, hi;
    {
        int a = 0, bb = N_NODES;
        while (a < bb) { int m = (a + bb) >> 1; if (batch[m] < g) a = m + 1; else bb = m; }
        lo = a;
        bb = N_NODES;
        while (a < bb) { int m = (a + bb) >> 1; if (batch[m] < g + 1) a = m + 1; else bb = m; }
        hi = a;
    }
    int cnt = hi - lo;
    float invc = 1.0f / fmaxf((float)cnt, 1.0f);

    int f = threadIdx.x & 63;
    int r = threadIdx.x >> 6;
    const int R = blockDim.x >> 6;

    __shared__ float red[1024];
    __shared__ float meanS[FDIM];
    __shared__ float invS[FDIM];

    // pass 1: mean
    float s = 0.f;
    for (int n = lo + r; n < hi; n += R) s += outv[(long)n * FDIM + f];
    red[threadIdx.x] = s;
    __syncthreads();
    if (r == 0) {
        float t = s;
        for (int i = 1; i < R; i++) t += red[i * 64 + f];
        meanS[f] = t * invc;
    }
    __syncthreads();

    float mc = meanS[f] * gms[f];

    // pass 2: variance of centered
    float v = 0.f;
    for (int n = lo + r; n < hi; n += R) {
        float c = outv[(long)n * FDIM + f] - mc;
        v += c * c;
    }
    __syncthreads();
    red[threadIdx.x] = v;
    __syncthreads();
    if (r == 0) {
        float t = v;
        for (int i = 1; i < R; i++) t += red[i * 64 + f];
        invS[f] = rsqrtf(t * invc + EPSV);
    }
    __syncthreads();

    // pass 3: normalize + residual relu + pooling
    float inv = invS[f];
    float wf = gw[f], bf = gb[f];
    float ps = 0.f, pm = -FLT_MAX;
    for (int n = lo + r; n < hi; n += R) {
        float c = outv[(long)n * FDIM + f] - mc;
        float hn = wf * c * inv + bf;
        float he = fmaxf(hn + x[(long)n * FDIM + f], 0.f);
        hemb[(long)n * FDIM + f] = he;
        ps += he;
        pm = fmaxf(pm, he);
    }
    __syncthreads();
    red[threadIdx.x] = ps;
    __syncthreads();
    if (r == 0) {
        float t = ps;
        for (int i = 1; i < R; i++) t += red[i * 64 + f];
        flat[g * 2 * FDIM + f] = t * invc;
    }
    __syncthreads();
    red[threadIdx.x] = pm;
    __syncthreads();
    if (r == 0) {
        float t = pm;
        for (int i = 1; i < R; i++) t = fmaxf(t, red[i * 64 + f]);
        flat[g * 2 * FDIM + FDIM + f] = t;
    }
}

// ---------------------------------------------------------------------------
extern "C" void kernel_launch(void* const* d_in, const int* in_sizes, int n_in,
                              void* d_out, int out_size) {
    const float* x     = (const float*)d_in[0];
    const int*   ei    = (const int*)d_in[1];
    const int*   batch = (const int*)d_in[2];
    const float* ew    = (const float*)d_in[3];
    const float* W     = (const float*)d_in[4];
    const float* b     = (const float*)d_in[5];
    const float* gw    = (const float*)d_in[6];
    const float* gb    = (const float*)d_in[7];
    const float* gms   = (const float*)d_in[8];

    float* hemb = (float*)d_out;
    float* flat = (float*)d_out + (size_t)N_NODES * FDIM;

    const int* src = ei;
    const int* dst = ei + N_EDGES;

    float *dDeg, *dNorm, *dH, *dOut;
    cudaGetSymbolAddress((void**)&dDeg,  g_deg);
    cudaGetSymbolAddress((void**)&dNorm, g_norm);
    cudaGetSymbolAddress((void**)&dH,    g_h);
    cudaGetSymbolAddress((void**)&dOut,  g_out);

    float* h1 = dH;
    float* h2 = dH + (size_t)N_NODES * FDIM;
    float* h3 = dH + 2 * (size_t)N_NODES * FDIM;

    // zero deg + hop buffers (N_NODES and N_NODES*FDIM divisible by 4)
    zero_kernel<<<512, 256>>>(dDeg, (long)N_NODES / 4);
    zero_kernel<<<4096, 256>>>(dH, 3L * N_NODES * FDIM / 4);

    const int EB = (N_EDGES + 255) / 256;
    const int NB = (N_NODES + 255) / 256;
    deg_kernel<<<EB, 256>>>(dst, ew, dDeg);
    dis_kernel<<<NB, 256>>>(dDeg);
    norm_kernel<<<EB, 256>>>(src, dst, ew, dDeg, dNorm);

    const int SPB = (N_EDGES * 16 + 255) / 256;   // 16 threads/edge
    spmm_kernel<<<SPB, 256>>>(x,  h1, src, dst, dNorm);
    spmm_kernel<<<SPB, 256>>>(h1, h2, src, dst, dNorm);
    spmm_kernel<<<SPB, 256>>>(h2, h3, src, dst, dNorm);

    const int GB = (N_NODES / 2 + 7) / 8;          // 8 warps/block, 2 nodes/warp
    gemm_kernel<<<GB, 256>>>(x,  W,             b, dOut, 0, 0);
    gemm_kernel<<<GB, 256>>>(h1, W + 64 * 64,   b, dOut, 1, 0);
    gemm_kernel<<<GB, 256>>>(h2, W + 2 * 64 * 64, b, dOut, 1, 0);
    gemm_kernel<<<GB, 256>>>(h3, W + 3 * 64 * 64, b, dOut, 1, 1);

    norm_pool_kernel<<<N_GRAPHS, 1024>>>(dOut, x, batch, gw, gb, gms, hemb, flat);
}

// round 6
// speedup vs baseline: 1.5164x; 1.5164x over previous
#include <cuda_runtime.h>
#include <math.h>
#include <float.h>

#define N_NODES 100000
#define N_EDGES 1600000
#define FDIM 64
#define N_GRAPHS 64
#define EPSV 1e-5f

#define SCAN_BLOCKS 98   // ceil(100000/1024)

typedef unsigned long long u64;

// ---------------- scratch (device globals; no allocation allowed) ----------
__device__ float g_deg[N_NODES];                 // deg, then deg^{-1/2} in place
__device__ int   g_cnt[N_NODES];                 // per-dst edge count
__device__ int   g_rowptr[N_NODES + 1];          // CSR row pointers (by dst)
__device__ int   g_fill[N_NODES];                // running fill cursors
__device__ int   g_bsum[128];                    // block sums for scan
__device__ int2  g_epack[N_EDGES];               // CSR payload: {src, bits(norm)}
__device__ float g_h[3][N_NODES * FDIM];         // h1, h2, h3
__device__ float g_out[N_NODES * FDIM];          // TAGConv output

// ---------------- f32x2 packed math helpers --------------------------------
__device__ __forceinline__ u64 pack2(float x, float y) {
    u64 r; asm("mov.b64 %0, {%1, %2};" : "=l"(r) : "f"(x), "f"(y)); return r;
}
__device__ __forceinline__ void fma2(u64& d, u64 a, u64 b) {
    asm("fma.rn.f32x2 %0, %1, %2, %0;" : "+l"(d) : "l"(a), "l"(b));
}
__device__ __forceinline__ float2 unpack2(u64 v) {
    float2 f; asm("mov.b64 {%0, %1}, %2;" : "=f"(f.x), "=f"(f.y) : "l"(v)); return f;
}

// ---------------- zero deg + cnt -------------------------------------------
__global__ void zero2_kernel() {
    int i = blockIdx.x * blockDim.x + threadIdx.x;
    if (i < N_NODES) { g_deg[i] = 0.f; g_cnt[i] = 0; }
}

// ---------------- degree + histogram in one edge pass ----------------------
__global__ void deg_hist_kernel(const int* __restrict__ dst, const float* __restrict__ ew) {
    int e = blockIdx.x * blockDim.x + threadIdx.x;
    if (e < N_EDGES) {
        int d = dst[e];
        atomicAdd(&g_deg[d], ew[e]);
        atomicAdd(&g_cnt[d], 1);
    }
}

// ---------------- deg -> deg^{-1/2} ----------------------------------------
__global__ void dis_kernel() {
    int i = blockIdx.x * blockDim.x + threadIdx.x;
    if (i < N_NODES) {
        float d = g_deg[i];
        g_deg[i] = (d > 0.f) ? rsqrtf(d) : 0.f;
    }
}

// ---------------- scan stage A: per-block sums of cnt ----------------------
__global__ __launch_bounds__(1024) void scanA_kernel() {
    __shared__ int sd[1024];
    int tid = threadIdx.x;
    int i = blockIdx.x * 1024 + tid;
    sd[tid] = (i < N_NODES) ? g_cnt[i] : 0;
    __syncthreads();
    for (int s = 512; s > 0; s >>= 1) {
        if (tid < s) sd[tid] += sd[tid + s];
        __syncthreads();
    }
    if (tid == 0) g_bsum[blockIdx.x] = sd[0];
}

// ---------------- scan stage B: exclusive scan of block sums ---------------
__global__ void scanB_kernel() {
    __shared__ int sb[128];
    int tid = threadIdx.x;
    sb[tid] = (tid < SCAN_BLOCKS) ? g_bsum[tid] : 0;
    __syncthreads();
    if (tid == 0) {
        int run = 0;
        for (int i = 0; i < SCAN_BLOCKS; i++) { int v = sb[i]; sb[i] = run; run += v; }
    }
    __syncthreads();
    if (tid < SCAN_BLOCKS) g_bsum[tid] = sb[tid];
}

// ---------------- scan stage C: per-element exclusive scan -> rowptr/fill --
__global__ __launch_bounds__(1024) void scanC_kernel() {
    __shared__ int sd[1024];
    int tid = threadIdx.x;
    int i = blockIdx.x * 1024 + tid;
    int v = (i < N_NODES) ? g_cnt[i] : 0;
    sd[tid] = v;
    __syncthreads();
    for (int off = 1; off < 1024; off <<= 1) {
        int tv = 0;
        if (tid >= off) tv = sd[tid - off];
        __syncthreads();
        sd[tid] += tv;
        __syncthreads();
    }
    int excl = sd[tid] - v + g_bsum[blockIdx.x];
    if (i < N_NODES) { g_rowptr[i] = excl; g_fill[i] = excl; }
    if (i == N_NODES - 1) g_rowptr[N_NODES] = excl + v;
}

// ---------------- CSR fill: compute norm + scatter edge payload ------------
__global__ void fill_kernel(const int* __restrict__ src, const int* __restrict__ dst,
                            const float* __restrict__ ew) {
    int e = blockIdx.x * blockDim.x + threadIdx.x;
    if (e < N_EDGES) {
        int s = src[e];
        int d = dst[e];
        float nrm = g_deg[s] * ew[e] * g_deg[d];   // g_deg holds deg^{-1/2}
        int pos = atomicAdd(&g_fill[d], 1);
        g_epack[pos] = make_int2(s, __float_as_int(nrm));
    }
}

// ---------------- hop: hout[n] = sum_{j in row(n)} norm_j * hin[src_j] -----
// 64-thread group per node; all gathers are coalesced 256B rows; no atomics.
__global__ __launch_bounds__(256) void hop_kernel(const float* __restrict__ hin,
                                                  float* __restrict__ hout) {
    int node = (blockIdx.x << 2) + (threadIdx.x >> 6);
    int f = threadIdx.x & 63;
    int lo = g_rowptr[node];
    int hi = g_rowptr[node + 1];
    float acc = 0.f;
    int j = lo;
    for (; j + 4 <= hi; j += 4) {
        int2 e0 = g_epack[j];
        int2 e1 = g_epack[j + 1];
        int2 e2 = g_epack[j + 2];
        int2 e3 = g_epack[j + 3];
        float v0 = hin[e0.x * FDIM + f];
        float v1 = hin[e1.x * FDIM + f];
        float v2 = hin[e2.x * FDIM + f];
        float v3 = hin[e3.x * FDIM + f];
        acc = fmaf(__int_as_float(e0.y), v0, acc);
        acc = fmaf(__int_as_float(e1.y), v1, acc);
        acc = fmaf(__int_as_float(e2.y), v2, acc);
        acc = fmaf(__int_as_float(e3.y), v3, acc);
    }
    for (; j < hi; j++) {
        int2 e = g_epack[j];
        acc = fmaf(__int_as_float(e.y), hin[e.x * FDIM + f], acc);
    }
    hout[node * FDIM + f] = acc;
}

// ---------------- fused GEMM: out = [x|h1|h2|h3] @ Wcat + b ----------------
// Block tile 128(M) x 64(N), K staged in 8 chunks of 32 (4 inputs x 2).
// Thread tile 8x4 with packed fma.rn.f32x2 (2x fp32 FMA rate).
#define GMM 128
#define KC 32
__global__ __launch_bounds__(256) void gemm_all_kernel(
        const float* __restrict__ x, const float* __restrict__ h1,
        const float* __restrict__ h2, const float* __restrict__ h3,
        const float* __restrict__ W, const float* __restrict__ b,
        float* __restrict__ out) {
    __shared__ __align__(16) float As[KC * GMM];   // swizzled [kk][m]
    __shared__ __align__(16) float Bs[KC * FDIM];  // [kk][n]
    int t = threadIdx.x;
    int mb = blockIdx.x * GMM;
    int tm = t >> 4, tn = t & 15;
    int m0 = tm * 8, n0 = tn * 4;

    u64 acc[4][4];
#pragma unroll
    for (int p = 0; p < 4; p++)
#pragma unroll
        for (int n = 0; n < 4; n++) acc[p][n] = 0ull;

    const float* Hs[4] = {x, h1, h2, h3};

    for (int kb = 0; kb < 4; kb++) {
        const float* H = Hs[kb];
        for (int ks = 0; ks < 2; ks++) {
            int ko = ks * KC;
            __syncthreads();
            // stage A tile: 128 nodes x 32 feats, transposed + swizzled
#pragma unroll
            for (int i = 0; i < 4; i++) {
                int f4i = i * 256 + t;          // 0..1023
                int m = f4i >> 3;               // node within tile
                int fc = (f4i & 7) << 2;        // feature chunk base (0..28)
                int node = mb + m;
                float4 v = (node < N_NODES)
                    ? *(const float4*)(H + (size_t)node * FDIM + ko + fc)
                    : make_float4(0.f, 0.f, 0.f, 0.f);
                int ms = m ^ ((fc >> 3) << 2);  // swizzle: 2-way max conflict
                As[(fc + 0) * GMM + ms] = v.x;
                As[(fc + 1) * GMM + ms] = v.y;
                As[(fc + 2) * GMM + ms] = v.z;
                As[(fc + 3) * GMM + ms] = v.w;
            }
            // stage B tile: W[kb] rows ko..ko+31 (row-major [j][n])
            const float4* Wk = (const float4*)(W + kb * FDIM * FDIM + ko * FDIM);
#pragma unroll
            for (int i = 0; i < 2; i++)
                ((float4*)Bs)[i * 256 + t] = Wk[i * 256 + t];
            __syncthreads();

#pragma unroll
            for (int kk = 0; kk < KC; kk++) {
                int xr = (kk >> 3) << 2;
                float4 a0 = *(const float4*)&As[kk * GMM + (m0 ^ xr)];
                float4 a1 = *(const float4*)&As[kk * GMM + ((m0 + 4) ^ xr)];
                float4 bv = *(const float4*)&Bs[kk * FDIM + n0];
                u64 ap[4] = {pack2(a0.x, a0.y), pack2(a0.z, a0.w),
                             pack2(a1.x, a1.y), pack2(a1.z, a1.w)};
                u64 bd[4] = {pack2(bv.x, bv.x), pack2(bv.y, bv.y),
                             pack2(bv.z, bv.z), pack2(bv.w, bv.w)};
#pragma unroll
                for (int p = 0; p < 4; p++)
#pragma unroll
                    for (int n = 0; n < 4; n++) fma2(acc[p][n], ap[p], bd[n]);
            }
        }
    }

    float4 bb = *(const float4*)(b + n0);
#pragma unroll
    for (int p = 0; p < 4; p++) {
        float2 c0 = unpack2(acc[p][0]);
        float2 c1 = unpack2(acc[p][1]);
        float2 c2 = unpack2(acc[p][2]);
        float2 c3 = unpack2(acc[p][3]);
        int me = mb + m0 + 2 * p;
        int mo = me + 1;
        if (me < N_NODES)
            *(float4*)(out + (size_t)me * FDIM + n0) =
                make_float4(c0.x + bb.x, c1.x + bb.y, c2.x + bb.z, c3.x + bb.w);
        if (mo < N_NODES)
            *(float4*)(out + (size_t)mo * FDIM + n0) =
                make_float4(c0.y + bb.x, c1.y + bb.y, c2.y + bb.z, c3.y + bb.w);
    }
}

// ---------------- GraphNorm (one-pass stats) + residual ReLU + pooling -----
__global__ __launch_bounds__(1024) void norm_pool_kernel(
        const float* __restrict__ outv, const float* __restrict__ x,
        const int* __restrict__ batch,
        const float* __restrict__ gw, const float* __restrict__ gb,
        const float* __restrict__ gms,
        float* __restrict__ hemb, float* __restrict__ flat) {
    int g = blockIdx.x;

    int lo, hi;
    {
        int a = 0, bb = N_NODES;
        while (a < bb) { int m = (a + bb) >> 1; if (batch[m] < g) a = m + 1; else bb = m; }
        lo = a;
        bb = N_NODES;
        while (a < bb) { int m = (a + bb) >> 1; if (batch[m] < g + 1) a = m + 1; else bb = m; }
        hi = a;
    }
    int cnt = hi - lo;
    float invc = 1.0f / fmaxf((float)cnt, 1.0f);

    int f = threadIdx.x & 63;
    int r = threadIdx.x >> 6;
    const int R = 1024 >> 6;

    __shared__ float red[1024];
    __shared__ float mcS[FDIM];
    __shared__ float invS[FDIM];
    __shared__ float meanS[FDIM];

    // single data pass: sum and sum of squares
    float s = 0.f, q = 0.f;
    for (int n = lo + r; n < hi; n += R) {
        float o = outv[(size_t)n * FDIM + f];
        s += o;
        q = fmaf(o, o, q);
    }
    red[threadIdx.x] = s;
    __syncthreads();
    if (r == 0) {
        float tt = red[f];
        for (int i = 1; i < R; i++) tt += red[i * 64 + f];
        meanS[f] = tt * invc;
    }
    __syncthreads();
    red[threadIdx.x] = q;
    __syncthreads();
    if (r == 0) {
        float tq = red[f];
        for (int i = 1; i < R; i++) tq += red[i * 64 + f];
        float mean = meanS[f];
        float mc = mean * gms[f];
        float var = tq * invc - 2.f * mc * mean + mc * mc;
        mcS[f] = mc;
        invS[f] = rsqrtf(var + EPSV);
    }
    __syncthreads();

    float mc = mcS[f];
    float inv = invS[f];
    float wf = gw[f], bf = gb[f];
    float ps = 0.f, pm = -FLT_MAX;
    for (int n = lo + r; n < hi; n += R) {
        float c = outv[(size_t)n * FDIM + f] - mc;
        float hn = wf * c * inv + bf;
        float he = fmaxf(hn + x[(size_t)n * FDIM + f], 0.f);
        hemb[(size_t)n * FDIM + f] = he;
        ps += he;
        pm = fmaxf(pm, he);
    }
    __syncthreads();
    red[threadIdx.x] = ps;
    __syncthreads();
    if (r == 0) {
        float tt = red[f];
        for (int i = 1; i < R; i++) tt += red[i * 64 + f];
        flat[g * 2 * FDIM + f] = tt * invc;
    }
    __syncthreads();
    red[threadIdx.x] = pm;
    __syncthreads();
    if (r == 0) {
        float tt = red[f];
        for (int i = 1; i < R; i++) tt = fmaxf(tt, red[i * 64 + f]);
        flat[g * 2 * FDIM + FDIM + f] = tt;
    }
}

// ---------------------------------------------------------------------------
extern "C" void kernel_launch(void* const* d_in, const int* in_sizes, int n_in,
                              void* d_out, int out_size) {
    const float* x     = (const float*)d_in[0];
    const int*   ei    = (const int*)d_in[1];
    const int*   batch = (const int*)d_in[2];
    const float* ew    = (const float*)d_in[3];
    const float* W     = (const float*)d_in[4];
    const float* b     = (const float*)d_in[5];
    const float* gw    = (const float*)d_in[6];
    const float* gb    = (const float*)d_in[7];
    const float* gms   = (const float*)d_in[8];

    float* hemb = (float*)d_out;
    float* flat = (float*)d_out + (size_t)N_NODES * FDIM;

    const int* src = ei;
    const int* dst = ei + N_EDGES;

    float* dH;
    cudaGetSymbolAddress((void**)&dH, g_h);
    float* h1 = dH;
    float* h2 = dH + (size_t)N_NODES * FDIM;
    float* h3 = dH + 2 * (size_t)N_NODES * FDIM;
    float* dOut;
    cudaGetSymbolAddress((void**)&dOut, g_out);

    const int EB = (N_EDGES + 255) / 256;

    // CSR build (by dst) + gcn normalization
    zero2_kernel<<<SCAN_BLOCKS, 1024>>>();
    deg_hist_kernel<<<EB, 256>>>(dst, ew);
    dis_kernel<<<(N_NODES + 255) / 256, 256>>>();
    scanA_kernel<<<SCAN_BLOCKS, 1024>>>();
    scanB_kernel<<<1, 128>>>();
    scanC_kernel<<<SCAN_BLOCKS, 1024>>>();
    fill_kernel<<<EB, 256>>>(src, dst, ew);

    // 3 propagation hops (gather form, no atomics)
    hop_kernel<<<N_NODES / 4, 256>>>(x,  h1);
    hop_kernel<<<N_NODES / 4, 256>>>(h1, h2);
    hop_kernel<<<N_NODES / 4, 256>>>(h2, h3);

    // fused 4-way GEMM + bias
    gemm_all_kernel<<<(N_NODES + GMM - 1) / GMM, 256>>>(x, h1, h2, h3, W, b, dOut);

    // GraphNorm + residual ReLU + mean/max pooling
    norm_pool_kernel<<<N_GRAPHS, 1024>>>(dOut, x, batch, gw, gb, gms, hemb, flat);
}

// round 7
// speedup vs baseline: 1.7630x; 1.1627x over previous
#include <cuda_runtime.h>
#include <math.h>
#include <float.h>

#define N_NODES 100000
#define N_EDGES 1600000
#define FDIM 64
#define N_GRAPHS 64
#define EPSV 1e-5f

#define SCAN_BLOCKS 98   // ceil(100000/1024)

typedef unsigned long long u64;
typedef unsigned int u32;

// ---------------- scratch (device globals; no allocation allowed) ----------
__device__ float2 g_degcnt[N_NODES];             // {weighted deg, count}
__device__ float g_dis[N_NODES];                 // deg^{-1/2}
__device__ int   g_cnt[N_NODES];                 // per-dst edge count (int)
__device__ int   g_rowptr[N_NODES + 1];          // CSR row pointers (by dst)
__device__ int   g_fill[N_NODES];                // running fill cursors
__device__ int   g_bsum[128];                    // block sums for scan
__device__ int2  g_epack[N_EDGES];               // CSR payload: {src, bits(norm)}
__device__ float g_h[3][N_NODES * FDIM];         // h1, h2, h3
__device__ float g_out[N_NODES * FDIM];          // TAGConv output
__device__ float g_sum[N_GRAPHS * FDIM];         // per-graph feature sums
__device__ float g_sumsq[N_GRAPHS * FDIM];       // per-graph feature sq-sums
__device__ float g_mc[N_GRAPHS * FDIM];          // mean * mean_scale
__device__ float g_a[N_GRAPHS * FDIM];           // gn_weight * rsqrt(var+eps)

// ---------------- f32x2 packed math helpers --------------------------------
__device__ __forceinline__ u64 pack2(float x, float y) {
    u64 r; asm("mov.b64 %0, {%1, %2};" : "=l"(r) : "f"(x), "f"(y)); return r;
}
__device__ __forceinline__ void fma2(u64& d, u64 a, u64 b) {
    asm("fma.rn.f32x2 %0, %1, %2, %0;" : "+l"(d) : "l"(a), "l"(b));
}
__device__ __forceinline__ float2 unpack2(u64 v) {
    float2 f; asm("mov.b64 {%0, %1}, %2;" : "=f"(f.x), "=f"(f.y) : "l"(v)); return f;
}

// ---------------- zero deg/cnt ---------------------------------------------
__global__ void zero2_kernel() {
    int i = blockIdx.x * blockDim.x + threadIdx.x;
    if (i < N_NODES) g_degcnt[i] = make_float2(0.f, 0.f);
}

// ---------------- zero per-graph stats + flat output region ----------------
__global__ void zero_stats_kernel(float* __restrict__ flat) {
    int i = blockIdx.x * blockDim.x + threadIdx.x;   // 0..16383
    if (i < N_GRAPHS * FDIM) { g_sum[i] = 0.f; g_sumsq[i] = 0.f; }
    if (i < N_GRAPHS * 2 * FDIM) flat[i] = 0.f;
}

// ---------------- degree + histogram: one vector red per edge --------------
__global__ void deg_hist_kernel(const int* __restrict__ dst, const float* __restrict__ ew) {
    int e = blockIdx.x * blockDim.x + threadIdx.x;
    if (e < N_EDGES) {
        int d = dst[e];
        float w = ew[e];
        float* addr = (float*)&g_degcnt[d];
        asm volatile("red.global.add.v2.f32 [%0], {%1, %2};"
                     :: "l"(addr), "f"(w), "f"(1.0f) : "memory");
    }
}

// ---------------- degcnt -> dis (deg^{-1/2}) + int cnt ---------------------
__global__ void dis_kernel() {
    int i = blockIdx.x * blockDim.x + threadIdx.x;
    if (i < N_NODES) {
        float2 dc = g_degcnt[i];
        g_dis[i] = (dc.x > 0.f) ? rsqrtf(dc.x) : 0.f;
        g_cnt[i] = (int)(dc.y + 0.5f);
    }
}

// ---------------- scan stage A: per-block sums of cnt ----------------------
__global__ __launch_bounds__(1024) void scanA_kernel() {
    __shared__ int sd[1024];
    int tid = threadIdx.x;
    int i = blockIdx.x * 1024 + tid;
    sd[tid] = (i < N_NODES) ? g_cnt[i] : 0;
    __syncthreads();
    for (int s = 512; s > 0; s >>= 1) {
        if (tid < s) sd[tid] += sd[tid + s];
        __syncthreads();
    }
    if (tid == 0) g_bsum[blockIdx.x] = sd[0];
}

// ---------------- scan stage B: exclusive scan of block sums ---------------
__global__ void scanB_kernel() {
    __shared__ int sb[128];
    int tid = threadIdx.x;
    sb[tid] = (tid < SCAN_BLOCKS) ? g_bsum[tid] : 0;
    __syncthreads();
    if (tid == 0) {
        int run = 0;
        for (int i = 0; i < SCAN_BLOCKS; i++) { int v = sb[i]; sb[i] = run; run += v; }
    }
    __syncthreads();
    if (tid < SCAN_BLOCKS) g_bsum[tid] = sb[tid];
}

// ---------------- scan stage C: per-element exclusive scan -> rowptr/fill --
__global__ __launch_bounds__(1024) void scanC_kernel() {
    __shared__ int sd[1024];
    int tid = threadIdx.x;
    int i = blockIdx.x * 1024 + tid;
    int v = (i < N_NODES) ? g_cnt[i] : 0;
    sd[tid] = v;
    __syncthreads();
    for (int off = 1; off < 1024; off <<= 1) {
        int tv = 0;
        if (tid >= off) tv = sd[tid - off];
        __syncthreads();
        sd[tid] += tv;
        __syncthreads();
    }
    int excl = sd[tid] - v + g_bsum[blockIdx.x];
    if (i < N_NODES) { g_rowptr[i] = excl; g_fill[i] = excl; }
    if (i == N_NODES - 1) g_rowptr[N_NODES] = excl + v;
}

// ---------------- CSR fill: compute norm + scatter edge payload ------------
__global__ void fill_kernel(const int* __restrict__ src, const int* __restrict__ dst,
                            const float* __restrict__ ew) {
    int e = blockIdx.x * blockDim.x + threadIdx.x;
    if (e < N_EDGES) {
        int s = src[e];
        int d = dst[e];
        float nrm = g_dis[s] * ew[e] * g_dis[d];
        int pos = atomicAdd(&g_fill[d], 1);
        g_epack[pos] = make_int2(s, __float_as_int(nrm));
    }
}

// ---------------- hop: hout[n] = sum_{j in row(n)} norm_j * hin[src_j] -----
// One warp per node, float2 per lane. Edge meta loaded once per warp
// (coalesced, lane-distributed) and broadcast via shfl -> LSU issue cut ~4x.
__global__ __launch_bounds__(256) void hop_kernel(const float* __restrict__ hin,
                                                  float* __restrict__ hout) {
    const unsigned FULL = 0xffffffffu;
    int warp = threadIdx.x >> 5;
    int lane = threadIdx.x & 31;
    int node = (blockIdx.x << 3) + warp;          // grid covers exactly 100000
    int lo = g_rowptr[node];
    int hi = g_rowptr[node + 1];
    const float2* __restrict__ hin2 = (const float2*)hin;
    float2 acc = make_float2(0.f, 0.f);

    for (int base = lo; base < hi; base += 32) {
        int n = hi - base; if (n > 32) n = 32;
        int2 e = make_int2(0, 0);
        if (lane < n) e = g_epack[base + lane];
        int j = 0;
        for (; j + 4 <= n; j += 4) {
            int s0 = __shfl_sync(FULL, e.x, j);
            int s1 = __shfl_sync(FULL, e.x, j + 1);
            int s2 = __shfl_sync(FULL, e.x, j + 2);
            int s3 = __shfl_sync(FULL, e.x, j + 3);
            float w0 = __int_as_float(__shfl_sync(FULL, e.y, j));
            float w1 = __int_as_float(__shfl_sync(FULL, e.y, j + 1));
            float w2 = __int_as_float(__shfl_sync(FULL, e.y, j + 2));
            float w3 = __int_as_float(__shfl_sync(FULL, e.y, j + 3));
            float2 v0 = hin2[s0 * 32 + lane];
            float2 v1 = hin2[s1 * 32 + lane];
            float2 v2 = hin2[s2 * 32 + lane];
            float2 v3 = hin2[s3 * 32 + lane];
            acc.x = fmaf(w0, v0.x, acc.x); acc.y = fmaf(w0, v0.y, acc.y);
            acc.x = fmaf(w1, v1.x, acc.x); acc.y = fmaf(w1, v1.y, acc.y);
            acc.x = fmaf(w2, v2.x, acc.x); acc.y = fmaf(w2, v2.y, acc.y);
            acc.x = fmaf(w3, v3.x, acc.x); acc.y = fmaf(w3, v3.y, acc.y);
        }
        for (; j < n; j++) {
            int s = __shfl_sync(FULL, e.x, j);
            float w = __int_as_float(__shfl_sync(FULL, e.y, j));
            float2 v = hin2[s * 32 + lane];
            acc.x = fmaf(w, v.x, acc.x); acc.y = fmaf(w, v.y, acc.y);
        }
    }
    ((float2*)hout)[node * 32 + lane] = acc;
}

// ---------------- fused GEMM: out = [x|h1|h2|h3] @ Wcat + b ----------------
#define GMM 128
#define KC 32
__global__ __launch_bounds__(256) void gemm_all_kernel(
        const float* __restrict__ x, const float* __restrict__ h1,
        const float* __restrict__ h2, const float* __restrict__ h3,
        const float* __restrict__ W, const float* __restrict__ b,
        float* __restrict__ out) {
    __shared__ __align__(16) float As[KC * GMM];   // swizzled [kk][m]
    __shared__ __align__(16) float Bs[KC * FDIM];  // [kk][n]
    int t = threadIdx.x;
    int mb = blockIdx.x * GMM;
    int tm = t >> 4, tn = t & 15;
    int m0 = tm * 8, n0 = tn * 4;

    u64 acc[4][4];
#pragma unroll
    for (int p = 0; p < 4; p++)
#pragma unroll
        for (int n = 0; n < 4; n++) acc[p][n] = 0ull;

    const float* Hs[4] = {x, h1, h2, h3};

    for (int kb = 0; kb < 4; kb++) {
        const float* H = Hs[kb];
        for (int ks = 0; ks < 2; ks++) {
            int ko = ks * KC;
            __syncthreads();
#pragma unroll
            for (int i = 0; i < 4; i++) {
                int f4i = i * 256 + t;
                int m = f4i >> 3;
                int fc = (f4i & 7) << 2;
                int node = mb + m;
                float4 v = (node < N_NODES)
                    ? *(const float4*)(H + (size_t)node * FDIM + ko + fc)
                    : make_float4(0.f, 0.f, 0.f, 0.f);
                int ms = m ^ ((fc >> 3) << 2);
                As[(fc + 0) * GMM + ms] = v.x;
                As[(fc + 1) * GMM + ms] = v.y;
                As[(fc + 2) * GMM + ms] = v.z;
                As[(fc + 3) * GMM + ms] = v.w;
            }
            const float4* Wk = (const float4*)(W + kb * FDIM * FDIM + ko * FDIM);
#pragma unroll
            for (int i = 0; i < 2; i++)
                ((float4*)Bs)[i * 256 + t] = Wk[i * 256 + t];
            __syncthreads();

#pragma unroll
            for (int kk = 0; kk < KC; kk++) {
                int xr = (kk >> 3) << 2;
                float4 a0 = *(const float4*)&As[kk * GMM + (m0 ^ xr)];
                float4 a1 = *(const float4*)&As[kk * GMM + ((m0 + 4) ^ xr)];
                float4 bv = *(const float4*)&Bs[kk * FDIM + n0];
                u64 ap[4] = {pack2(a0.x, a0.y), pack2(a0.z, a0.w),
                             pack2(a1.x, a1.y), pack2(a1.z, a1.w)};
                u64 bd[4] = {pack2(bv.x, bv.x), pack2(bv.y, bv.y),
                             pack2(bv.z, bv.z), pack2(bv.w, bv.w)};
#pragma unroll
                for (int p = 0; p < 4; p++)
#pragma unroll
                    for (int n = 0; n < 4; n++) fma2(acc[p][n], ap[p], bd[n]);
            }
        }
    }

    float4 bb = *(const float4*)(b + n0);
#pragma unroll
    for (int p = 0; p < 4; p++) {
        float2 c0 = unpack2(acc[p][0]);
        float2 c1 = unpack2(acc[p][1]);
        float2 c2 = unpack2(acc[p][2]);
        float2 c3 = unpack2(acc[p][3]);
        int me = mb + m0 + 2 * p;
        int mo = me + 1;
        if (me < N_NODES)
            *(float4*)(out + (size_t)me * FDIM + n0) =
                make_float4(c0.x + bb.x, c1.x + bb.y, c2.x + bb.z, c3.x + bb.w);
        if (mo < N_NODES)
            *(float4*)(out + (size_t)mo * FDIM + n0) =
                make_float4(c0.y + bb.x, c1.y + bb.y, c2.y + bb.z, c3.y + bb.w);
    }
}

// ---------------- graph range lookup (batch is sorted) ---------------------
__device__ __forceinline__ void graph_range(const int* __restrict__ batch, int g,
                                            int& lo, int& hi) {
    int a = 0, bb = N_NODES;
    while (a < bb) { int m = (a + bb) >> 1; if (batch[m] < g) a = m + 1; else bb = m; }
    lo = a;
    bb = N_NODES;
    while (a < bb) { int m = (a + bb) >> 1; if (batch[m] < g + 1) a = m + 1; else bb = m; }
    hi = a;
}

// ---------------- NP1: per-graph-quarter sum / sumsq partials --------------
// Grid 256: block = g*4+q. 256 threads: f = tid&63, r = tid>>6 (4 rows).
__global__ __launch_bounds__(256) void stats_kernel(const float* __restrict__ outv,
                                                    const int* __restrict__ batch) {
    int g = blockIdx.x >> 2;
    int q = blockIdx.x & 3;
    int lo, hi;
    graph_range(batch, g, lo, hi);
    int cnt = hi - lo;
    int qlo = lo + (int)(((long)cnt * q) >> 2);
    int qhi = lo + (int)(((long)cnt * (q + 1)) >> 2);

    int f = threadIdx.x & 63;
    int r = threadIdx.x >> 6;
    float s = 0.f, sq = 0.f;
    for (int n = qlo + r; n < qhi; n += 4) {
        float o = outv[(size_t)n * FDIM + f];
        s += o;
        sq = fmaf(o, o, sq);
    }
    __shared__ float red[256];
    red[threadIdx.x] = s;
    __syncthreads();
    if (r == 0) {
        float t = red[f] + red[64 + f] + red[128 + f] + red[192 + f];
        atomicAdd(&g_sum[g * FDIM + f], t);
    }
    __syncthreads();
    red[threadIdx.x] = sq;
    __syncthreads();
    if (r == 0) {
        float t = red[f] + red[64 + f] + red[128 + f] + red[192 + f];
        atomicAdd(&g_sumsq[g * FDIM + f], t);
    }
}

// ---------------- NP2: finalize stats -> mc, a -----------------------------
__global__ void finalize_kernel(const int* __restrict__ batch,
                                const float* __restrict__ gw,
                                const float* __restrict__ gb_unused,
                                const float* __restrict__ gms) {
    int g = blockIdx.x;
    int f = threadIdx.x;
    int lo, hi;
    graph_range(batch, g, lo, hi);
    float invc = 1.0f / fmaxf((float)(hi - lo), 1.0f);
    float mean = g_sum[g * FDIM + f] * invc;
    float mc = mean * gms[f];
    float var = g_sumsq[g * FDIM + f] * invc - 2.f * mc * mean + mc * mc;
    g_mc[g * FDIM + f] = mc;
    g_a[g * FDIM + f] = gw[f] * rsqrtf(var + EPSV);
}

// ---------------- NP3: apply + residual ReLU + pooled partials -------------
__global__ __launch_bounds__(256) void apply_pool_kernel(
        const float* __restrict__ outv, const float* __restrict__ x,
        const int* __restrict__ batch, const float* __restrict__ gb,
        float* __restrict__ hemb, float* __restrict__ flat) {
    int g = blockIdx.x >> 2;
    int q = blockIdx.x & 3;
    int lo, hi;
    graph_range(batch, g, lo, hi);
    int cnt = hi - lo;
    float invc = 1.0f / fmaxf((float)cnt, 1.0f);
    int qlo = lo + (int)(((long)cnt * q) >> 2);
    int qhi = lo + (int)(((long)cnt * (q + 1)) >> 2);

    int f = threadIdx.x & 63;
    int r = threadIdx.x >> 6;
    float mc = g_mc[g * FDIM + f];
    float a = g_a[g * FDIM + f];
    float bf = gb[f];

    float ps = 0.f, pm = 0.f;   // relu output >= 0 -> 0 is a safe max identity
    for (int n = qlo + r; n < qhi; n += 4) {
        float c = outv[(size_t)n * FDIM + f] - mc;
        float hn = fmaf(a, c, bf);
        float he = fmaxf(hn + x[(size_t)n * FDIM + f], 0.f);
        hemb[(size_t)n * FDIM + f] = he;
        ps += he;
        pm = fmaxf(pm, he);
    }
    __shared__ float red[256];
    red[threadIdx.x] = ps;
    __syncthreads();
    if (r == 0) {
        float t = red[f] + red[64 + f] + red[128 + f] + red[192 + f];
        atomicAdd(&flat[g * 2 * FDIM + f], t * invc);
    }
    __syncthreads();
    red[threadIdx.x] = pm;
    __syncthreads();
    if (r == 0) {
        float t = fmaxf(fmaxf(red[f], red[64 + f]), fmaxf(red[128 + f], red[192 + f]));
        atomicMax((u32*)&flat[g * 2 * FDIM + FDIM + f], __float_as_uint(t));
    }
}

// ---------------------------------------------------------------------------
extern "C" void kernel_launch(void* const* d_in, const int* in_sizes, int n_in,
                              void* d_out, int out_size) {
    const float* x     = (const float*)d_in[0];
    const int*   ei    = (const int*)d_in[1];
    const int*   batch = (const int*)d_in[2];
    const float* ew    = (const float*)d_in[3];
    const float* W     = (const float*)d_in[4];
    const float* b     = (const float*)d_in[5];
    const float* gw    = (const float*)d_in[6];
    const float* gb    = (const float*)d_in[7];
    const float* gms   = (const float*)d_in[8];

    float* hemb = (float*)d_out;
    float* flat = (float*)d_out + (size_t)N_NODES * FDIM;

    const int* src = ei;
    const int* dst = ei + N_EDGES;

    float* dH;
    cudaGetSymbolAddress((void**)&dH, g_h);
    float* h1 = dH;
    float* h2 = dH + (size_t)N_NODES * FDIM;
    float* h3 = dH + 2 * (size_t)N_NODES * FDIM;
    float* dOut;
    cudaGetSymbolAddress((void**)&dOut, g_out);

    const int EB = (N_EDGES + 255) / 256;

    // CSR build (by dst) + gcn normalization
    zero2_kernel<<<SCAN_BLOCKS, 1024>>>();
    zero_stats_kernel<<<16, 1024>>>(flat);
    deg_hist_kernel<<<EB, 256>>>(dst, ew);
    dis_kernel<<<(N_NODES + 255) / 256, 256>>>();
    scanA_kernel<<<SCAN_BLOCKS, 1024>>>();
    scanB_kernel<<<1, 128>>>();
    scanC_kernel<<<SCAN_BLOCKS, 1024>>>();
    fill_kernel<<<EB, 256>>>(src, dst, ew);

    // 3 propagation hops (gather form, warp-per-node, shfl meta broadcast)
    hop_kernel<<<N_NODES / 8, 256>>>(x,  h1);
    hop_kernel<<<N_NODES / 8, 256>>>(h1, h2);
    hop_kernel<<<N_NODES / 8, 256>>>(h2, h3);

    // fused 4-way GEMM + bias
    gemm_all_kernel<<<(N_NODES + GMM - 1) / GMM, 256>>>(x, h1, h2, h3, W, b, dOut);

    // GraphNorm + residual ReLU + pooling (3 stages, full-chip parallelism)
    stats_kernel<<<N_GRAPHS * 4, 256>>>(dOut, batch);
    finalize_kernel<<<N_GRAPHS, FDIM>>>(batch, gw, gb, gms);
    apply_pool_kernel<<<N_GRAPHS * 4, 256>>>(dOut, x, batch, gb, hemb, flat);
}

// round 8
// speedup vs baseline: 2.1015x; 1.1920x over previous
#include <cuda_runtime.h>
#include <cuda_fp16.h>
#include <math.h>
#include <float.h>

#define N_NODES 100000
#define N_EDGES 1600000
#define FDIM 64
#define N_GRAPHS 64
#define EPSV 1e-5f

#define SCAN_BLOCKS 98   // ceil(100000/1024)

typedef unsigned long long u64;
typedef unsigned int u32;

// ---------------- scratch (device globals; no allocation allowed) ----------
__device__ float2 g_degcnt[N_NODES];             // {weighted deg, count}
__device__ float g_dis[N_NODES];                 // deg^{-1/2}
__device__ int   g_cnt[N_NODES];                 // per-dst edge count (int)
__device__ int   g_rowptr[N_NODES + 1];          // CSR row pointers (by dst)
__device__ int   g_fill[N_NODES];                // running fill cursors
__device__ int   g_bsum[128];                    // block sums for scan
__device__ int2  g_epack[N_EDGES];               // CSR payload: {src, bits(norm)}
__device__ __half2 g_xh[N_NODES * FDIM / 2];     // fp16 copy of x
__device__ __half2 g_h16[3][N_NODES * FDIM / 2]; // h1, h2, h3 (fp16)
__device__ float g_out[N_NODES * FDIM];          // TAGConv output
__device__ float g_sum[N_GRAPHS * FDIM];         // per-graph feature sums
__device__ float g_sumsq[N_GRAPHS * FDIM];       // per-graph feature sq-sums
__device__ float g_mc[N_GRAPHS * FDIM];          // mean * mean_scale
__device__ float g_a[N_GRAPHS * FDIM];           // gn_weight * rsqrt(var+eps)

// ---------------- f32x2 packed math helpers --------------------------------
__device__ __forceinline__ u64 pack2(float x, float y) {
    u64 r; asm("mov.b64 %0, {%1, %2};" : "=l"(r) : "f"(x), "f"(y)); return r;
}
__device__ __forceinline__ void fma2(u64& d, u64 a, u64 b) {
    asm("fma.rn.f32x2 %0, %1, %2, %0;" : "+l"(d) : "l"(a), "l"(b));
}
__device__ __forceinline__ float2 unpack2(u64 v) {
    float2 f; asm("mov.b64 {%0, %1}, %2;" : "=f"(f.x), "=f"(f.y) : "l"(v)); return f;
}

// ---------------- zero degcnt + stats + flat (fused) -----------------------
__global__ __launch_bounds__(1024) void zero_all_kernel(float* __restrict__ flat) {
    int i = blockIdx.x * blockDim.x + threadIdx.x;
    if (i < N_NODES) g_degcnt[i] = make_float2(0.f, 0.f);
    if (i < N_GRAPHS * FDIM) { g_sum[i] = 0.f; g_sumsq[i] = 0.f; }
    if (i < N_GRAPHS * 2 * FDIM) flat[i] = 0.f;
}

// ---------------- degree + histogram: one vector red per edge --------------
__global__ void deg_hist_kernel(const int* __restrict__ dst, const float* __restrict__ ew) {
    int e = blockIdx.x * blockDim.x + threadIdx.x;
    if (e < N_EDGES) {
        int d = dst[e];
        float w = ew[e];
        float* addr = (float*)&g_degcnt[d];
        asm volatile("red.global.add.v2.f32 [%0], {%1, %2};"
                     :: "l"(addr), "f"(w), "f"(1.0f) : "memory");
    }
}

// ---------------- fused: degcnt -> dis + int cnt + scan stage A ------------
__global__ __launch_bounds__(1024) void dis_scanA_kernel() {
    __shared__ int sd[1024];
    int tid = threadIdx.x;
    int i = blockIdx.x * 1024 + tid;
    int c = 0;
    if (i < N_NODES) {
        float2 dc = g_degcnt[i];
        g_dis[i] = (dc.x > 0.f) ? rsqrtf(dc.x) : 0.f;
        c = (int)(dc.y + 0.5f);
        g_cnt[i] = c;
    }
    sd[tid] = c;
    __syncthreads();
    for (int s = 512; s > 0; s >>= 1) {
        if (tid < s) sd[tid] += sd[tid + s];
        __syncthreads();
    }
    if (tid == 0) g_bsum[blockIdx.x] = sd[0];
}

// ---------------- scan stage B: exclusive scan of block sums ---------------
__global__ void scanB_kernel() {
    __shared__ int sb[128];
    int tid = threadIdx.x;
    sb[tid] = (tid < SCAN_BLOCKS) ? g_bsum[tid] : 0;
    __syncthreads();
    if (tid == 0) {
        int run = 0;
        for (int i = 0; i < SCAN_BLOCKS; i++) { int v = sb[i]; sb[i] = run; run += v; }
    }
    __syncthreads();
    if (tid < SCAN_BLOCKS) g_bsum[tid] = sb[tid];
}

// ---------------- scan stage C: per-element exclusive scan -> rowptr/fill --
__global__ __launch_bounds__(1024) void scanC_kernel() {
    __shared__ int sd[1024];
    int tid = threadIdx.x;
    int i = blockIdx.x * 1024 + tid;
    int v = (i < N_NODES) ? g_cnt[i] : 0;
    sd[tid] = v;
    __syncthreads();
    for (int off = 1; off < 1024; off <<= 1) {
        int tv = 0;
        if (tid >= off) tv = sd[tid - off];
        __syncthreads();
        sd[tid] += tv;
        __syncthreads();
    }
    int excl = sd[tid] - v + g_bsum[blockIdx.x];
    if (i < N_NODES) { g_rowptr[i] = excl; g_fill[i] = excl; }
    if (i == N_NODES - 1) g_rowptr[N_NODES] = excl + v;
}

// ---------------- CSR fill: compute norm + scatter edge payload ------------
__global__ void fill_kernel(const int* __restrict__ src, const int* __restrict__ dst,
                            const float* __restrict__ ew) {
    int e = blockIdx.x * blockDim.x + threadIdx.x;
    if (e < N_EDGES) {
        int s = src[e];
        int d = dst[e];
        float nrm = g_dis[s] * ew[e] * g_dis[d];
        int pos = atomicAdd(&g_fill[d], 1);
        g_epack[pos] = make_int2(s, __float_as_int(nrm));
    }
}

// ---------------- x -> fp16 copy -------------------------------------------
__global__ __launch_bounds__(256) void xconv_kernel(const float* __restrict__ x) {
    int i = blockIdx.x * blockDim.x + threadIdx.x;   // over half2 elements
    const float2* x2 = (const float2*)x;
    if (i < N_NODES * FDIM / 2) g_xh[i] = __float22half2_rn(x2[i]);
}

// ---------------- hop: hout[n] = sum_{j in row(n)} norm_j * hin[src_j] -----
// One warp per node; lane owns a half2 feature pair (128B coalesced gather).
// Edge meta loaded once per warp (lane-distributed) and broadcast via shfl.
// fp32 accumulate, fp16 store.
__global__ __launch_bounds__(256) void hop_kernel(const __half2* __restrict__ hin2,
                                                  __half2* __restrict__ hout2) {
    const unsigned FULL = 0xffffffffu;
    int warp = threadIdx.x >> 5;
    int lane = threadIdx.x & 31;
    int node = (blockIdx.x << 3) + warp;          // grid covers exactly 100000
    int lo = g_rowptr[node];
    int hi = g_rowptr[node + 1];
    float2 acc = make_float2(0.f, 0.f);

    for (int base = lo; base < hi; base += 32) {
        int n = hi - base; if (n > 32) n = 32;
        int2 e = make_int2(0, 0);
        if (lane < n) e = g_epack[base + lane];
        int j = 0;
        for (; j + 4 <= n; j += 4) {
            int s0 = __shfl_sync(FULL, e.x, j);
            int s1 = __shfl_sync(FULL, e.x, j + 1);
            int s2 = __shfl_sync(FULL, e.x, j + 2);
            int s3 = __shfl_sync(FULL, e.x, j + 3);
            float w0 = __int_as_float(__shfl_sync(FULL, e.y, j));
            float w1 = __int_as_float(__shfl_sync(FULL, e.y, j + 1));
            float w2 = __int_as_float(__shfl_sync(FULL, e.y, j + 2));
            float w3 = __int_as_float(__shfl_sync(FULL, e.y, j + 3));
            __half2 v0 = hin2[s0 * 32 + lane];
            __half2 v1 = hin2[s1 * 32 + lane];
            __half2 v2 = hin2[s2 * 32 + lane];
            __half2 v3 = hin2[s3 * 32 + lane];
            float2 f0 = __half22float2(v0);
            float2 f1 = __half22float2(v1);
            float2 f2 = __half22float2(v2);
            float2 f3 = __half22float2(v3);
            acc.x = fmaf(w0, f0.x, acc.x); acc.y = fmaf(w0, f0.y, acc.y);
            acc.x = fmaf(w1, f1.x, acc.x); acc.y = fmaf(w1, f1.y, acc.y);
            acc.x = fmaf(w2, f2.x, acc.x); acc.y = fmaf(w2, f2.y, acc.y);
            acc.x = fmaf(w3, f3.x, acc.x); acc.y = fmaf(w3, f3.y, acc.y);
        }
        for (; j < n; j++) {
            int s = __shfl_sync(FULL, e.x, j);
            float w = __int_as_float(__shfl_sync(FULL, e.y, j));
            float2 f = __half22float2(hin2[s * 32 + lane]);
            acc.x = fmaf(w, f.x, acc.x); acc.y = fmaf(w, f.y, acc.y);
        }
    }
    hout2[node * 32 + lane] = __float22half2_rn(acc);
}

// ---------------- fused GEMM: out = x@W0 + h1@W1 + h2@W2 + h3@W3 + b -------
// x read fp32; h1..h3 read fp16 and widened during smem staging.
#define GMM 128
#define KC 32
__global__ __launch_bounds__(256) void gemm_all_kernel(
        const float* __restrict__ x,
        const __half* __restrict__ h1, const __half* __restrict__ h2,
        const __half* __restrict__ h3,
        const float* __restrict__ W, const float* __restrict__ b,
        float* __restrict__ out) {
    __shared__ __align__(16) float As[KC * GMM];   // swizzled [kk][m]
    __shared__ __align__(16) float Bs[KC * FDIM];  // [kk][n]
    int t = threadIdx.x;
    int mb = blockIdx.x * GMM;
    int tm = t >> 4, tn = t & 15;
    int m0 = tm * 8, n0 = tn * 4;

    u64 acc[4][4];
#pragma unroll
    for (int p = 0; p < 4; p++)
#pragma unroll
        for (int n = 0; n < 4; n++) acc[p][n] = 0ull;

    const __half* Hh[3] = {h1, h2, h3};

    for (int kb = 0; kb < 4; kb++) {
        for (int ks = 0; ks < 2; ks++) {
            int ko = ks * KC;
            __syncthreads();
#pragma unroll
            for (int i = 0; i < 4; i++) {
                int f4i = i * 256 + t;
                int m = f4i >> 3;
                int fc = (f4i & 7) << 2;
                int node = mb + m;
                float4 v = make_float4(0.f, 0.f, 0.f, 0.f);
                if (node < N_NODES) {
                    if (kb == 0) {
                        v = *(const float4*)(x + (size_t)node * FDIM + ko + fc);
                    } else {
                        const __half* H = Hh[kb - 1];
                        uint2 r = *(const uint2*)(H + (size_t)node * FDIM + ko + fc);
                        float2 a = __half22float2(*(__half2*)&r.x);
                        float2 c = __half22float2(*(__half2*)&r.y);
                        v = make_float4(a.x, a.y, c.x, c.y);
                    }
                }
                int ms = m ^ ((fc >> 3) << 2);
                As[(fc + 0) * GMM + ms] = v.x;
                As[(fc + 1) * GMM + ms] = v.y;
                As[(fc + 2) * GMM + ms] = v.z;
                As[(fc + 3) * GMM + ms] = v.w;
            }
            const float4* Wk = (const float4*)(W + kb * FDIM * FDIM + ko * FDIM);
#pragma unroll
            for (int i = 0; i < 2; i++)
                ((float4*)Bs)[i * 256 + t] = Wk[i * 256 + t];
            __syncthreads();

#pragma unroll
            for (int kk = 0; kk < KC; kk++) {
                int xr = (kk >> 3) << 2;
                float4 a0 = *(const float4*)&As[kk * GMM + (m0 ^ xr)];
                float4 a1 = *(const float4*)&As[kk * GMM + ((m0 + 4) ^ xr)];
                float4 bv = *(const float4*)&Bs[kk * FDIM + n0];
                u64 ap[4] = {pack2(a0.x, a0.y), pack2(a0.z, a0.w),
                             pack2(a1.x, a1.y), pack2(a1.z, a1.w)};
                u64 bd[4] = {pack2(bv.x, bv.x), pack2(bv.y, bv.y),
                             pack2(bv.z, bv.z), pack2(bv.w, bv.w)};
#pragma unroll
                for (int p = 0; p < 4; p++)
#pragma unroll
                    for (int n = 0; n < 4; n++) fma2(acc[p][n], ap[p], bd[n]);
            }
        }
    }

    float4 bb = *(const float4*)(b + n0);
#pragma unroll
    for (int p = 0; p < 4; p++) {
        float2 c0 = unpack2(acc[p][0]);
        float2 c1 = unpack2(acc[p][1]);
        float2 c2 = unpack2(acc[p][2]);
        float2 c3 = unpack2(acc[p][3]);
        int me = mb + m0 + 2 * p;
        int mo = me + 1;
        if (me < N_NODES)
            *(float4*)(out + (size_t)me * FDIM + n0) =
                make_float4(c0.x + bb.x, c1.x + bb.y, c2.x + bb.z, c3.x + bb.w);
        if (mo < N_NODES)
            *(float4*)(out + (size_t)mo * FDIM + n0) =
                make_float4(c0.y + bb.x, c1.y + bb.y, c2.y + bb.z, c3.y + bb.w);
    }
}

// ---------------- graph range lookup (batch is sorted) ---------------------
__device__ __forceinline__ void graph_range(const int* __restrict__ batch, int g,
                                            int& lo, int& hi) {
    int a = 0, bb = N_NODES;
    while (a < bb) { int m = (a + bb) >> 1; if (batch[m] < g) a = m + 1; else bb = m; }
    lo = a;
    bb = N_NODES;
    while (a < bb) { int m = (a + bb) >> 1; if (batch[m] < g + 1) a = m + 1; else bb = m; }
    hi = a;
}

#define NCHUNK 16   // chunks per graph for stats/apply

// ---------------- NP1: per-chunk sum / sumsq partials ----------------------
__global__ __launch_bounds__(256) void stats_kernel(const float* __restrict__ outv,
                                                    const int* __restrict__ batch) {
    int g = blockIdx.x / NCHUNK;
    int q = blockIdx.x % NCHUNK;
    int lo, hi;
    graph_range(batch, g, lo, hi);
    int cnt = hi - lo;
    int qlo = lo + (int)(((long)cnt * q) / NCHUNK);
    int qhi = lo + (int)(((long)cnt * (q + 1)) / NCHUNK);

    int f = threadIdx.x & 63;
    int r = threadIdx.x >> 6;
    float s = 0.f, sq = 0.f;
    for (int n = qlo + r; n < qhi; n += 4) {
        float o = outv[(size_t)n * FDIM + f];
        s += o;
        sq = fmaf(o, o, sq);
    }
    __shared__ float red[256];
    red[threadIdx.x] = s;
    __syncthreads();
    if (r == 0) {
        float t = red[f] + red[64 + f] + red[128 + f] + red[192 + f];
        atomicAdd(&g_sum[g * FDIM + f], t);
    }
    __syncthreads();
    red[threadIdx.x] = sq;
    __syncthreads();
    if (r == 0) {
        float t = red[f] + red[64 + f] + red[128 + f] + red[192 + f];
        atomicAdd(&g_sumsq[g * FDIM + f], t);
    }
}

// ---------------- NP2: finalize stats -> mc, a -----------------------------
__global__ void finalize_kernel(const int* __restrict__ batch,
                                const float* __restrict__ gw,
                                const float* __restrict__ gms) {
    int g = blockIdx.x;
    int f = threadIdx.x;
    int lo, hi;
    graph_range(batch, g, lo, hi);
    float invc = 1.0f / fmaxf((float)(hi - lo), 1.0f);
    float mean = g_sum[g * FDIM + f] * invc;
    float mc = mean * gms[f];
    float var = g_sumsq[g * FDIM + f] * invc - 2.f * mc * mean + mc * mc;
    g_mc[g * FDIM + f] = mc;
    g_a[g * FDIM + f] = gw[f] * rsqrtf(var + EPSV);
}

// ---------------- NP3: apply + residual ReLU + pooled partials -------------
__global__ __launch_bounds__(256) void apply_pool_kernel(
        const float* __restrict__ outv, const float* __restrict__ x,
        const int* __restrict__ batch, const float* __restrict__ gb,
        float* __restrict__ hemb, float* __restrict__ flat) {
    int g = blockIdx.x / NCHUNK;
    int q = blockIdx.x % NCHUNK;
    int lo, hi;
    graph_range(batch, g, lo, hi);
    int cnt = hi - lo;
    float invc = 1.0f / fmaxf((float)cnt, 1.0f);
    int qlo = lo + (int)(((long)cnt * q) / NCHUNK);
    int qhi = lo + (int)(((long)cnt * (q + 1)) / NCHUNK);

    int f = threadIdx.x & 63;
    int r = threadIdx.x >> 6;
    float mc = g_mc[g * FDIM + f];
    float a = g_a[g * FDIM + f];
    float bf = gb[f];

    float ps = 0.f, pm = 0.f;   // relu output >= 0 -> 0 is a safe max identity
    for (int n = qlo + r; n < qhi; n += 4) {
        float c = outv[(size_t)n * FDIM + f] - mc;
        float hn = fmaf(a, c, bf);
        float he = fmaxf(hn + x[(size_t)n * FDIM + f], 0.f);
        hemb[(size_t)n * FDIM + f] = he;
        ps += he;
        pm = fmaxf(pm, he);
    }
    __shared__ float red[256];
    red[threadIdx.x] = ps;
    __syncthreads();
    if (r == 0) {
        float t = red[f] + red[64 + f] + red[128 + f] + red[192 + f];
        atomicAdd(&flat[g * 2 * FDIM + f], t * invc);
    }
    __syncthreads();
    red[threadIdx.x] = pm;
    __syncthreads();
    if (r == 0) {
        float t = fmaxf(fmaxf(red[f], red[64 + f]), fmaxf(red[128 + f], red[192 + f]));
        atomicMax((u32*)&flat[g * 2 * FDIM + FDIM + f], __float_as_uint(t));
    }
}

// ---------------------------------------------------------------------------
extern "C" void kernel_launch(void* const* d_in, const int* in_sizes, int n_in,
                              void* d_out, int out_size) {
    const float* x     = (const float*)d_in[0];
    const int*   ei    = (const int*)d_in[1];
    const int*   batch = (const int*)d_in[2];
    const float* ew    = (const float*)d_in[3];
    const float* W     = (const float*)d_in[4];
    const float* b     = (const float*)d_in[5];
    const float* gw    = (const float*)d_in[6];
    const float* gb    = (const float*)d_in[7];
    const float* gms   = (const float*)d_in[8];

    float* hemb = (float*)d_out;
    float* flat = (float*)d_out + (size_t)N_NODES * FDIM;

    const int* src = ei;
    const int* dst = ei + N_EDGES;

    __half2* dXh;
    cudaGetSymbolAddress((void**)&dXh, g_xh);
    __half2* dH;
    cudaGetSymbolAddress((void**)&dH, g_h16);
    __half2* h1 = dH;
    __half2* h2 = dH + (size_t)N_NODES * FDIM / 2;
    __half2* h3 = dH + 2 * ((size_t)N_NODES * FDIM / 2);
    float* dOut;
    cudaGetSymbolAddress((void**)&dOut, g_out);

    const int EB = (N_EDGES + 255) / 256;

    // CSR build (by dst) + gcn normalization + fp16 x copy
    zero_all_kernel<<<SCAN_BLOCKS, 1024>>>(flat);
    xconv_kernel<<<(N_NODES * FDIM / 2 + 255) / 256, 256>>>(x);
    deg_hist_kernel<<<EB, 256>>>(dst, ew);
    dis_scanA_kernel<<<SCAN_BLOCKS, 1024>>>();
    scanB_kernel<<<1, 128>>>();
    scanC_kernel<<<SCAN_BLOCKS, 1024>>>();
    fill_kernel<<<EB, 256>>>(src, dst, ew);

    // 3 propagation hops (fp16 gather, fp32 accumulate)
    hop_kernel<<<N_NODES / 8, 256>>>(dXh, h1);
    hop_kernel<<<N_NODES / 8, 256>>>(h1,  h2);
    hop_kernel<<<N_NODES / 8, 256>>>(h2,  h3);

    // fused 4-way GEMM + bias (x fp32, h fp16->fp32)
    gemm_all_kernel<<<(N_NODES + GMM - 1) / GMM, 256>>>(
        x, (const __half*)h1, (const __half*)h2, (const __half*)h3, W, b, dOut);

    // GraphNorm + residual ReLU + pooling
    stats_kernel<<<N_GRAPHS * NCHUNK, 256>>>(dOut, batch);
    finalize_kernel<<<N_GRAPHS, FDIM>>>(batch, gw, gms);
    apply_pool_kernel<<<N_GRAPHS * NCHUNK, 256>>>(dOut, x, batch, gb, hemb, flat);
}

// round 11
// speedup vs baseline: 2.4701x; 1.1754x over previous
#include <cuda_runtime.h>
#include <cuda_fp16.h>
#include <math.h>
#include <float.h>

#define N_NODES 100000
#define N_EDGES 1600000
#define FDIM 64
#define N_GRAPHS 64
#define EPSV 1e-5f

#define SCAN_BLOCKS 98   // ceil(100000/1024)

typedef unsigned long long u64;
typedef unsigned int u32;

// ---------------- scratch (device globals; no allocation allowed) ----------
__device__ float2 g_degcnt[N_NODES];             // {weighted deg, count}
__device__ float g_dis[N_NODES];                 // deg^{-1/2}
__device__ int   g_cnt[N_NODES];                 // per-dst edge count (int)
__device__ int   g_rowptr[N_NODES + 1];          // CSR row pointers (by dst)
__device__ int   g_fill[N_NODES];                // running fill cursors
__device__ int   g_bsum[128];                    // block sums for scan
__device__ int2  g_epack[N_EDGES];               // CSR payload: {src, bits(norm)}
__device__ __half2 g_xh[N_NODES * FDIM / 2];     // fp16 copy of x
__device__ __half2 g_h16[3][N_NODES * FDIM / 2]; // h1, h2, h3 (fp16)
__device__ float g_out[N_NODES * FDIM];          // TAGConv output
__device__ float g_sum[N_GRAPHS * FDIM];         // per-graph feature sums
__device__ float g_sumsq[N_GRAPHS * FDIM];       // per-graph feature sq-sums
__device__ float g_mc[N_GRAPHS * FDIM];          // mean * mean_scale
__device__ float g_a[N_GRAPHS * FDIM];           // gn_weight * rsqrt(var+eps)

// ---------------- zero degcnt + stats + flat (fused) -----------------------
__global__ __launch_bounds__(1024) void zero_all_kernel(float* __restrict__ flat) {
    int i = blockIdx.x * blockDim.x + threadIdx.x;
    if (i < N_NODES) g_degcnt[i] = make_float2(0.f, 0.f);
    if (i < N_GRAPHS * FDIM) { g_sum[i] = 0.f; g_sumsq[i] = 0.f; }
    if (i < N_GRAPHS * 2 * FDIM) flat[i] = 0.f;
}

// ---------------- degree + histogram: one vector red per edge --------------
__global__ void deg_hist_kernel(const int* __restrict__ dst, const float* __restrict__ ew) {
    int e = blockIdx.x * blockDim.x + threadIdx.x;
    if (e < N_EDGES) {
        int d = dst[e];
        float w = ew[e];
        float* addr = (float*)&g_degcnt[d];
        asm volatile("red.global.add.v2.f32 [%0], {%1, %2};"
                     :: "l"(addr), "f"(w), "f"(1.0f) : "memory");
    }
}

// ---------------- fused: degcnt -> dis + int cnt + scan stage A ------------
__global__ __launch_bounds__(1024) void dis_scanA_kernel() {
    __shared__ int sd[1024];
    int tid = threadIdx.x;
    int i = blockIdx.x * 1024 + tid;
    int c = 0;
    if (i < N_NODES) {
        float2 dc = g_degcnt[i];
        g_dis[i] = (dc.x > 0.f) ? rsqrtf(dc.x) : 0.f;
        c = (int)(dc.y + 0.5f);
        g_cnt[i] = c;
    }
    sd[tid] = c;
    __syncthreads();
    for (int s = 512; s > 0; s >>= 1) {
        if (tid < s) sd[tid] += sd[tid + s];
        __syncthreads();
    }
    if (tid == 0) g_bsum[blockIdx.x] = sd[0];
}

// ---------------- scan stage B: exclusive scan of block sums ---------------
__global__ void scanB_kernel() {
    __shared__ int sb[128];
    int tid = threadIdx.x;
    sb[tid] = (tid < SCAN_BLOCKS) ? g_bsum[tid] : 0;
    __syncthreads();
    if (tid == 0) {
        int run = 0;
        for (int i = 0; i < SCAN_BLOCKS; i++) { int v = sb[i]; sb[i] = run; run += v; }
    }
    __syncthreads();
    if (tid < SCAN_BLOCKS) g_bsum[tid] = sb[tid];
}

// ---------------- scan stage C: per-element exclusive scan -> rowptr/fill --
__global__ __launch_bounds__(1024) void scanC_kernel() {
    __shared__ int sd[1024];
    int tid = threadIdx.x;
    int i = blockIdx.x * 1024 + tid;
    int v = (i < N_NODES) ? g_cnt[i] : 0;
    sd[tid] = v;
    __syncthreads();
    for (int off = 1; off < 1024; off <<= 1) {
        int tv = 0;
        if (tid >= off) tv = sd[tid - off];
        __syncthreads();
        sd[tid] += tv;
        __syncthreads();
    }
    int excl = sd[tid] - v + g_bsum[blockIdx.x];
    if (i < N_NODES) { g_rowptr[i] = excl; g_fill[i] = excl; }
    if (i == N_NODES - 1) g_rowptr[N_NODES] = excl + v;
}

// ---------------- CSR fill: compute norm + scatter edge payload ------------
__global__ void fill_kernel(const int* __restrict__ src, const int* __restrict__ dst,
                            const float* __restrict__ ew) {
    int e = blockIdx.x * blockDim.x + threadIdx.x;
    if (e < N_EDGES) {
        int s = src[e];
        int d = dst[e];
        float nrm = g_dis[s] * ew[e] * g_dis[d];
        int pos = atomicAdd(&g_fill[d], 1);
        g_epack[pos] = make_int2(s, __float_as_int(nrm));
    }
}

// ---------------- x -> fp16 copy -------------------------------------------
__global__ __launch_bounds__(256) void xconv_kernel(const float* __restrict__ x) {
    int i = blockIdx.x * blockDim.x + threadIdx.x;   // over half2 elements
    const float2* x2 = (const float2*)x;
    if (i < N_NODES * FDIM / 2) g_xh[i] = __float22half2_rn(x2[i]);
}

// ---------------- hop: hout[n] = sum_{j in row(n)} norm_j * hin[src_j] -----
// One warp per node; lane owns a half2 feature pair (128B coalesced gather).
// Edge meta loaded once per warp (lane-distributed) and broadcast via shfl.
// fp32 accumulate, fp16 store.
__global__ __launch_bounds__(256) void hop_kernel(const __half2* __restrict__ hin2,
                                                  __half2* __restrict__ hout2) {
    const unsigned FULL = 0xffffffffu;
    int warp = threadIdx.x >> 5;
    int lane = threadIdx.x & 31;
    int node = (blockIdx.x << 3) + warp;          // grid covers exactly 100000
    int lo = g_rowptr[node];
    int hi = g_rowptr[node + 1];
    float2 acc = make_float2(0.f, 0.f);

    for (int base = lo; base < hi; base += 32) {
        int n = hi - base; if (n > 32) n = 32;
        int2 e = make_int2(0, 0);
        if (lane < n) e = g_epack[base + lane];
        int j = 0;
        for (; j + 4 <= n; j += 4) {
            int s0 = __shfl_sync(FULL, e.x, j);
            int s1 = __shfl_sync(FULL, e.x, j + 1);
            int s2 = __shfl_sync(FULL, e.x, j + 2);
            int s3 = __shfl_sync(FULL, e.x, j + 3);
            float w0 = __int_as_float(__shfl_sync(FULL, e.y, j));
            float w1 = __int_as_float(__shfl_sync(FULL, e.y, j + 1));
            float w2 = __int_as_float(__shfl_sync(FULL, e.y, j + 2));
            float w3 = __int_as_float(__shfl_sync(FULL, e.y, j + 3));
            __half2 v0 = hin2[s0 * 32 + lane];
            __half2 v1 = hin2[s1 * 32 + lane];
            __half2 v2 = hin2[s2 * 32 + lane];
            __half2 v3 = hin2[s3 * 32 + lane];
            float2 f0 = __half22float2(v0);
            float2 f1 = __half22float2(v1);
            float2 f2 = __half22float2(v2);
            float2 f3 = __half22float2(v3);
            acc.x = fmaf(w0, f0.x, acc.x); acc.y = fmaf(w0, f0.y, acc.y);
            acc.x = fmaf(w1, f1.x, acc.x); acc.y = fmaf(w1, f1.y, acc.y);
            acc.x = fmaf(w2, f2.x, acc.x); acc.y = fmaf(w2, f2.y, acc.y);
            acc.x = fmaf(w3, f3.x, acc.x); acc.y = fmaf(w3, f3.y, acc.y);
        }
        for (; j < n; j++) {
            int s = __shfl_sync(FULL, e.x, j);
            float w = __int_as_float(__shfl_sync(FULL, e.y, j));
            float2 f = __half22float2(hin2[s * 32 + lane]);
            acc.x = fmaf(w, f.x, acc.x); acc.y = fmaf(w, f.y, acc.y);
        }
    }
    hout2[node * 32 + lane] = __float22half2_rn(acc);
}

// ---------------- HMMA GEMM: out = [xh|h1|h2|h3](fp16) @ W(fp16) + b -------
// mma.sync.m16n8k16 f16*f16 -> f32. Block tile 128x64, 8 warps (16x64 each).
// W staged fp32->fp16 transposed into padded smem (pitch 264 -> bank 4g+t,
// conflict-free). A fragments load straight from global (16B segments share
// 32B sectors between a0/a2 -> L1 hits; no A smem, no per-chunk syncs).
#define BPITCH 264
__global__ __launch_bounds__(256) void gemm_hmma_kernel(
        const __half* __restrict__ xh,
        const __half* __restrict__ h1, const __half* __restrict__ h2,
        const __half* __restrict__ h3,
        const float* __restrict__ W, const float* __restrict__ b,
        float* __restrict__ out) {
    __shared__ __align__(16) __half Bst[FDIM * BPITCH];   // [n][k], k=0..255
    int t = threadIdx.x;

    // stage W transposed: Bst[n][k] = (half)W[k*64+n]
    for (int i = t; i < 256 * FDIM; i += 256) {
        int k = i >> 6, n = i & 63;
        Bst[n * BPITCH + k] = __float2half(W[i]);
    }
    __syncthreads();

    int warp = t >> 5, lane = t & 31;
    int g = lane >> 2, tq = lane & 3;
    int m0 = blockIdx.x * 128 + warp * 16;
    int rA = m0 + g;            // rows this thread touches
    int rB = m0 + g + 8;
    bool okA = rA < N_NODES;
    bool okB = rB < N_NODES;

    float acc[8][4];
#pragma unroll
    for (int nt = 0; nt < 8; nt++)
#pragma unroll
        for (int c = 0; c < 4; c++) acc[nt][c] = 0.f;

    const __half* Hs[4] = {xh, h1, h2, h3};

#pragma unroll
    for (int kb = 0; kb < 4; kb++) {
        const __half* H = Hs[kb];
        const __half* rowa = H + (size_t)rA * FDIM;
        const __half* rowb = H + (size_t)rB * FDIM;
#pragma unroll
        for (int jc = 0; jc < 4; jc++) {
            int kl = jc * 16 + tq * 2;
            unsigned a0 = okA ? *(const unsigned*)&rowa[kl]     : 0u;
            unsigned a2 = okA ? *(const unsigned*)&rowa[kl + 8] : 0u;
            unsigned a1 = okB ? *(const unsigned*)&rowb[kl]     : 0u;
            unsigned a3 = okB ? *(const unsigned*)&rowb[kl + 8] : 0u;
            int kg = kb * 64 + kl;
#pragma unroll
            for (int nt = 0; nt < 8; nt++) {
                int n = nt * 8 + g;
                unsigned b0 = *(const unsigned*)&Bst[n * BPITCH + kg];
                unsigned b1 = *(const unsigned*)&Bst[n * BPITCH + kg + 8];
                asm volatile(
                    "mma.sync.aligned.m16n8k16.row.col.f32.f16.f16.f32 "
                    "{%0,%1,%2,%3}, {%4,%5,%6,%7}, {%8,%9}, {%0,%1,%2,%3};"
                    : "+f"(acc[nt][0]), "+f"(acc[nt][1]),
                      "+f"(acc[nt][2]), "+f"(acc[nt][3])
                    : "r"(a0), "r"(a1), "r"(a2), "r"(a3), "r"(b0), "r"(b1));
            }
        }
    }

    // epilogue: add bias, write fp32
#pragma unroll
    for (int nt = 0; nt < 8; nt++) {
        int col = nt * 8 + tq * 2;
        float2 bb = *(const float2*)&b[col];
        if (okA)
            *(float2*)&out[(size_t)rA * FDIM + col] =
                make_float2(acc[nt][0] + bb.x, acc[nt][1] + bb.y);
        if (okB)
            *(float2*)&out[(size_t)rB * FDIM + col] =
                make_float2(acc[nt][2] + bb.x, acc[nt][3] + bb.y);
    }
}

// ---------------- graph range lookup (batch is sorted) ---------------------
__device__ __forceinline__ void graph_range(const int* __restrict__ batch, int g,
                                            int& lo, int& hi) {
    int a = 0, bb = N_NODES;
    while (a < bb) { int m = (a + bb) >> 1; if (batch[m] < g) a = m + 1; else bb = m; }
    lo = a;
    bb = N_NODES;
    while (a < bb) { int m = (a + bb) >> 1; if (batch[m] < g + 1) a = m + 1; else bb = m; }
    hi = a;
}

#define NCHUNK 16   // chunks per graph for stats/apply

// ---------------- NP1: per-chunk sum / sumsq partials ----------------------
__global__ __launch_bounds__(256) void stats_kernel(const float* __restrict__ outv,
                                                    const int* __restrict__ batch) {
    int g = blockIdx.x / NCHUNK;
    int q = blockIdx.x % NCHUNK;
    int lo, hi;
    graph_range(batch, g, lo, hi);
    int cnt = hi - lo;
    int qlo = lo + (int)(((long)cnt * q) / NCHUNK);
    int qhi = lo + (int)(((long)cnt * (q + 1)) / NCHUNK);

    int f = threadIdx.x & 63;
    int r = threadIdx.x >> 6;
    float s = 0.f, sq = 0.f;
    for (int n = qlo + r; n < qhi; n += 4) {
        float o = outv[(size_t)n * FDIM + f];
        s += o;
        sq = fmaf(o, o, sq);
    }
    __shared__ float red[256];
    red[threadIdx.x] = s;
    __syncthreads();
    if (r == 0) {
        float t = red[f] + red[64 + f] + red[128 + f] + red[192 + f];
        atomicAdd(&g_sum[g * FDIM + f], t);
    }
    __syncthreads();
    red[threadIdx.x] = sq;
    __syncthreads();
    if (r == 0) {
        float t = red[f] + red[64 + f] + red[128 + f] + red[192 + f];
        atomicAdd(&g_sumsq[g * FDIM + f], t);
    }
}

// ---------------- NP2: finalize stats -> mc, a -----------------------------
__global__ void finalize_kernel(const int* __restrict__ batch,
                                const float* __restrict__ gw,
                                const float* __restrict__ gms) {
    int g = blockIdx.x;
    int f = threadIdx.x;
    int lo, hi;
    graph_range(batch, g, lo, hi);
    float invc = 1.0f / fmaxf((float)(hi - lo), 1.0f);
    float mean = g_sum[g * FDIM + f] * invc;
    float mc = mean * gms[f];
    float var = g_sumsq[g * FDIM + f] * invc - 2.f * mc * mean + mc * mc;
    g_mc[g * FDIM + f] = mc;
    g_a[g * FDIM + f] = gw[f] * rsqrtf(var + EPSV);
}

// ---------------- NP3: apply + residual ReLU + pooled partials -------------
__global__ __launch_bounds__(256) void apply_pool_kernel(
        const float* __restrict__ outv, const float* __restrict__ x,
        const int* __restrict__ batch, const float* __restrict__ gb,
        float* __restrict__ hemb, float* __restrict__ flat) {
    int g = blockIdx.x / NCHUNK;
    int q = blockIdx.x % NCHUNK;
    int lo, hi;
    graph_range(batch, g, lo, hi);
    int cnt = hi - lo;
    float invc = 1.0f / fmaxf((float)cnt, 1.0f);
    int qlo = lo + (int)(((long)cnt * q) / NCHUNK);
    int qhi = lo + (int)(((long)cnt * (q + 1)) / NCHUNK);

    int f = threadIdx.x & 63;
    int r = threadIdx.x >> 6;
    float mc = g_mc[g * FDIM + f];
    float a = g_a[g * FDIM + f];
    float bf = gb[f];

    float ps = 0.f, pm = 0.f;   // relu output >= 0 -> 0 is a safe max identity
    for (int n = qlo + r; n < qhi; n += 4) {
        float c = outv[(size_t)n * FDIM + f] - mc;
        float hn = fmaf(a, c, bf);
        float he = fmaxf(hn + x[(size_t)n * FDIM + f], 0.f);
        hemb[(size_t)n * FDIM + f] = he;
        ps += he;
        pm = fmaxf(pm, he);
    }
    __shared__ float red[256];
    red[threadIdx.x] = ps;
    __syncthreads();
    if (r == 0) {
        float t = red[f] + red[64 + f] + red[128 + f] + red[192 + f];
        atomicAdd(&flat[g * 2 * FDIM + f], t * invc);
    }
    __syncthreads();
    red[threadIdx.x] = pm;
    __syncthreads();
    if (r == 0) {
        float t = fmaxf(fmaxf(red[f], red[64 + f]), fmaxf(red[128 + f], red[192 + f]));
        atomicMax((u32*)&flat[g * 2 * FDIM + FDIM + f], __float_as_uint(t));
    }
}

// ---------------------------------------------------------------------------
extern "C" void kernel_launch(void* const* d_in, const int* in_sizes, int n_in,
                              void* d_out, int out_size) {
    const float* x     = (const float*)d_in[0];
    const int*   ei    = (const int*)d_in[1];
    const int*   batch = (const int*)d_in[2];
    const float* ew    = (const float*)d_in[3];
    const float* W     = (const float*)d_in[4];
    const float* b     = (const float*)d_in[5];
    const float* gw    = (const float*)d_in[6];
    const float* gb    = (const float*)d_in[7];
    const float* gms   = (const float*)d_in[8];

    float* hemb = (float*)d_out;
    float* flat = (float*)d_out + (size_t)N_NODES * FDIM;

    const int* src = ei;
    const int* dst = ei + N_EDGES;

    __half2* dXh;
    cudaGetSymbolAddress((void**)&dXh, g_xh);
    __half2* dH;
    cudaGetSymbolAddress((void**)&dH, g_h16);
    __half2* h1 = dH;
    __half2* h2 = dH + (size_t)N_NODES * FDIM / 2;
    __half2* h3 = dH + 2 * ((size_t)N_NODES * FDIM / 2);
    float* dOut;
    cudaGetSymbolAddress((void**)&dOut, g_out);

    const int EB = (N_EDGES + 255) / 256;

    // CSR build (by dst) + gcn normalization + fp16 x copy
    zero_all_kernel<<<SCAN_BLOCKS, 1024>>>(flat);
    xconv_kernel<<<(N_NODES * FDIM / 2 + 255) / 256, 256>>>(x);
    deg_hist_kernel<<<EB, 256>>>(dst, ew);
    dis_scanA_kernel<<<SCAN_BLOCKS, 1024>>>();
    scanB_kernel<<<1, 128>>>();
    scanC_kernel<<<SCAN_BLOCKS, 1024>>>();
    fill_kernel<<<EB, 256>>>(src, dst, ew);

    // 3 propagation hops (fp16 gather, fp32 accumulate)
    hop_kernel<<<N_NODES / 8, 256>>>(dXh, h1);
    hop_kernel<<<N_NODES / 8, 256>>>(h1,  h2);
    hop_kernel<<<N_NODES / 8, 256>>>(h2,  h3);

    // tensor-core GEMM: out = [xh|h1|h2|h3] @ W + b
    gemm_hmma_kernel<<<(N_NODES + 127) / 128, 256>>>(
        (const __half*)dXh, (const __half*)h1, (const __half*)h2,
        (const __half*)h3, W, b, dOut);

    // GraphNorm + residual ReLU + pooling
    stats_kernel<<<N_GRAPHS * NCHUNK, 256>>>(dOut, batch);
    finalize_kernel<<<N_GRAPHS, FDIM>>>(batch, gw, gms);
    apply_pool_kernel<<<N_GRAPHS * NCHUNK, 256>>>(dOut, x, batch, gb, hemb, flat);
}